// round 9
// baseline (speedup 1.0000x reference)
#include <cuda_runtime.h>
#include <math.h>

#define MAXSPAN 66
#define WSTRIDE 72            // padded x-weight stride
#define NRL     1024          // R(256) * 4 levels

struct Params {
    const float* feat[4];
    int H[4];
    int W[4];
    float scale[4];
    int C;
};

// Scratch (allocation-free rule: __device__ globals)
__device__ float              g_wy[NRL * WSTRIDE];
__device__ float              g_wx[NRL * WSTRIDE];   // zero-padded, 4-aligned window
__device__ int4               g_meta[NRL];           // {ny, nx4, base_off, 0}
__device__ unsigned long long g_magic[NRL];          // ceil(2^32/nx4), 64-bit

// Warp-parallel prep: one block per (roi,level); warp0 = Y axis, warp1 = X axis.
__global__ __launch_bounds__(64)
void prep_kernel(Params p, const float* __restrict__ boxes) {
    const int rl  = blockIdx.x;
    const int r   = rl >> 2;
    const int lvl = rl & 3;

    __shared__ float s_wlo[2][32], s_whi[2][32];
    __shared__ int   s_slo[2][32], s_shi[2][32];
    __shared__ int   sh_y0, sh_ny, sh_x0al, sh_nx4;

    const int warp = threadIdx.x >> 5, lane = threadIdx.x & 31;
    const int axis = warp;                        // 0 = Y, 1 = X
    const float scale = p.scale[lvl];
    const int L = axis ? p.W[lvl] : p.H[lvl];
    float c1 = __fmul_rn(boxes[r * 4 + (axis ? 0 : 1)], scale);
    float c2 = __fmul_rn(boxes[r * 4 + (axis ? 2 : 3)], scale);
    float sz  = fmaxf(__fadd_rn(c2, -c1), 1.0f);
    float bin = __fdiv_rn(sz, 14.0f);

    const int s = lane;                           // lanes 28..31 inert
    float off = (float)(s >> 1) + ((float)(s & 1) + 0.5f) * 0.5f;
    float v   = __fadd_rn(c1, __fmul_rn(off, bin));
    bool valid = (s < 28) && (v >= -1.0f) && (v <= (float)L);
    v = fmaxf(v, 0.0f);
    int lo = (int)v;                              // floor, v >= 0
    int hi; float fr;
    if (lo >= L - 1) { lo = L - 1; hi = L - 1; fr = 0.0f; }
    else             { hi = lo + 1; fr = v - (float)lo; }
    s_slo[axis][lane] = lo;
    s_shi[axis][lane] = hi;
    s_wlo[axis][lane] = valid ? (1.0f - fr) : 0.0f;
    s_whi[axis][lane] = valid ? fr : 0.0f;

    int mnv = valid ? lo : 0x7fffffff;
    int mxv = valid ? hi : -1;
#pragma unroll
    for (int o = 16; o; o >>= 1) {
        mnv = min(mnv, __shfl_xor_sync(0xffffffffu, mnv, o));
        mxv = max(mxv, __shfl_xor_sync(0xffffffffu, mxv, o));
    }
    int n = (mxv < 0) ? 0 : (mxv - mnv + 1);
    if (n > MAXSPAN) n = MAXSPAN;
    if (mxv < 0) mnv = 0;
    __syncwarp();

    if (axis == 0) {
        float* wy = &g_wy[rl * WSTRIDE];
        for (int j = lane; j < n; j += 32) {
            int idx = mnv + j;
            float w = 0.0f;
            for (int t = 0; t < 28; t++) {        // matches reference sum order
                if (s_slo[0][t] == idx) w += s_wlo[0][t];
                if (s_shi[0][t] == idx) w += s_whi[0][t];
            }
            wy[j] = w * (1.0f / 28.0f);
        }
        if (lane == 0) { sh_y0 = mnv; sh_ny = n; }
    } else {
        int x0al  = mnv & ~3;
        int shift = mnv - x0al;
        int nxp   = (n > 0) ? ((shift + n + 3) & ~3) : 0;
        float* wx = &g_wx[rl * WSTRIDE];
        for (int j = lane; j < nxp; j += 32) {
            int k = j - shift;
            float w = 0.0f;
            if (k >= 0 && k < n) {
                int idx = mnv + k;
                for (int t = 0; t < 28; t++) {
                    if (s_slo[1][t] == idx) w += s_wlo[1][t];
                    if (s_shi[1][t] == idx) w += s_whi[1][t];
                }
            }
            wx[j] = w * (1.0f / 28.0f);
        }
        if (lane == 0) { sh_x0al = x0al; sh_nx4 = nxp >> 2; }
    }
    __syncthreads();
    if (threadIdx.x == 0) {
        int ny  = sh_ny;
        int nx4 = sh_nx4;
        g_meta[rl] = make_int4(ny, nx4, sh_y0 * p.W[lvl] + sh_x0al, 0);
        int d = nx4 > 0 ? nx4 : 1;
        g_magic[rl] = (0x100000000ULL + (unsigned long long)d - 1) /
                      (unsigned long long)d;
    }
}

// grid (R*4, 8). 128 threads = 4 warps; channel group = 32 channels;
// each warp: 8 channels in 2 passes of 4. Register-squeezed: min 10 blocks/SM.
__global__ __launch_bounds__(128, 10)
void roi_main_kernel(Params p, const int* __restrict__ bids,
                     float* __restrict__ out) {
    const int rl  = blockIdx.x;
    const int lvl = rl & 3;
    const int r   = rl >> 2;
    const int W   = p.W[lvl];
    const int HW  = p.H[lvl] * W;
    const int C   = p.C;

    __shared__ float  s_wy[MAXSPAN];
    __shared__ float4 s_wx4[WSTRIDE / 4];

    const int4 m = g_meta[rl];
    const int ny = m.x, nx4 = m.y;
    const unsigned long long magic = g_magic[rl];

    const int tid = threadIdx.x;
    for (int i = tid; i < ny; i += 128) s_wy[i] = g_wy[rl * WSTRIDE + i];
    for (int i = tid; i < nx4; i += 128)
        s_wx4[i] = ((const float4*)&g_wx[rl * WSTRIDE])[i];
    __syncthreads();

    const int total = ny * nx4;
    const int b = __ldg(&bids[r]);
    const float* __restrict__ fb = p.feat[lvl] + (size_t)b * C * HW + m.z;

    const int warp = tid >> 5, lane = tid & 31;
    const int cbase = blockIdx.y * 32 + warp * 8;
    const int outbase = r * 4 * C + lvl * C;
    const unsigned W4  = (unsigned)(W >> 2);
    const int      HW4 = HW >> 2;                 // channel stride in float4s

#pragma unroll
    for (int k = 0; k < 2; k++) {
        const int c = cbase + k * 4;
        const float4* __restrict__ f0 = (const float4*)(fb + (size_t)c * HW);
        float a0 = 0.f, a1 = 0.f, a2 = 0.f, a3 = 0.f;
        for (int i = lane; i < total; i += 32) {
            unsigned yy  = (unsigned)(((unsigned long long)(unsigned)i * magic) >> 32);
            unsigned xx4 = (unsigned)i - yy * (unsigned)nx4;
            int off = (int)(yy * W4 + xx4);
            float4 v0 = __ldg(f0 + off);
            float4 v1 = __ldg(f0 + off + HW4);
            float4 v2 = __ldg(f0 + off + 2 * HW4);
            float4 v3 = __ldg(f0 + off + 3 * HW4);
            float  wy = s_wy[yy];
            float4 wx = s_wx4[xx4];
            float w0 = wy * wx.x, w1 = wy * wx.y, w2 = wy * wx.z, w3 = wy * wx.w;
            a0 = fmaf(w0, v0.x, fmaf(w1, v0.y, fmaf(w2, v0.z, fmaf(w3, v0.w, a0))));
            a1 = fmaf(w0, v1.x, fmaf(w1, v1.y, fmaf(w2, v1.z, fmaf(w3, v1.w, a1))));
            a2 = fmaf(w0, v2.x, fmaf(w1, v2.y, fmaf(w2, v2.z, fmaf(w3, v2.w, a2))));
            a3 = fmaf(w0, v3.x, fmaf(w1, v3.y, fmaf(w2, v3.z, fmaf(w3, v3.w, a3))));
        }
#pragma unroll
        for (int o = 16; o; o >>= 1) {
            a0 += __shfl_xor_sync(0xffffffffu, a0, o);
            a1 += __shfl_xor_sync(0xffffffffu, a1, o);
            a2 += __shfl_xor_sync(0xffffffffu, a2, o);
            a3 += __shfl_xor_sync(0xffffffffu, a3, o);
        }
        if (lane == 0) {
            out[outbase + c + 0] = a0;
            out[outbase + c + 1] = a1;
            out[outbase + c + 2] = a2;
            out[outbase + c + 3] = a3;
        }
    }
}

extern "C" void kernel_launch(void* const* d_in, const int* in_sizes, int n_in,
                              void* d_out, int out_size) {
    const int B = 2, C = 256;
    Params p;
    for (int i = 0; i < 4; i++) {
        p.feat[i] = (const float*)d_in[i];
        long npix = (long)in_sizes[i] / ((long)B * C);
        int Hh = (int)(sqrt((double)npix * 5.0 / 8.0) + 0.5);  // 800:1280 aspect
        int Ww = (int)(npix / Hh);
        p.H[i] = Hh;
        p.W[i] = Ww;
        p.scale[i] = 0.25f / (float)(1 << i);
    }
    p.C = C;
    const int R = in_sizes[4] / 4;
    const float* boxes = (const float*)d_in[4];
    const int*   bids  = (const int*)d_in[5];

    prep_kernel<<<R * 4, 64>>>(p, boxes);
    roi_main_kernel<<<dim3(R * 4, 8), 128>>>(p, bids, (float*)d_out);
}

// round 10
// speedup vs baseline: 1.0229x; 1.0229x over previous
#include <cuda_runtime.h>
#include <math.h>

#define MAXSPAN 66
#define WSTRIDE 72            // padded x-weight stride
#define NRL     1024          // R(256) * 4 levels

struct Params {
    const float* feat[4];
    int H[4];
    int W[4];
    float scale[4];
    int C;
};

// Scratch (allocation-free rule: __device__ globals)
__device__ float              g_wy[NRL * WSTRIDE];
__device__ float              g_wx[NRL * WSTRIDE];   // zero-padded, 4-aligned window
__device__ int4               g_meta[NRL];           // {ny, nx4, base_off, 0}
__device__ unsigned long long g_magic[NRL];          // ceil(2^32/nx4), 64-bit

// Warp-parallel prep: one block per (roi,level); warp0 = Y axis, warp1 = X axis.
__global__ __launch_bounds__(64)
void prep_kernel(Params p, const float* __restrict__ boxes) {
    const int rl  = blockIdx.x;
    const int r   = rl >> 2;
    const int lvl = rl & 3;

    __shared__ float s_wlo[2][32], s_whi[2][32];
    __shared__ int   s_slo[2][32], s_shi[2][32];
    __shared__ int   sh_y0, sh_ny, sh_x0al, sh_nx4;

    const int warp = threadIdx.x >> 5, lane = threadIdx.x & 31;
    const int axis = warp;                        // 0 = Y, 1 = X
    const float scale = p.scale[lvl];
    const int L = axis ? p.W[lvl] : p.H[lvl];
    float c1 = __fmul_rn(boxes[r * 4 + (axis ? 0 : 1)], scale);
    float c2 = __fmul_rn(boxes[r * 4 + (axis ? 2 : 3)], scale);
    float sz  = fmaxf(__fadd_rn(c2, -c1), 1.0f);
    float bin = __fdiv_rn(sz, 14.0f);

    const int s = lane;                           // lanes 28..31 inert
    float off = (float)(s >> 1) + ((float)(s & 1) + 0.5f) * 0.5f;
    float v   = __fadd_rn(c1, __fmul_rn(off, bin));
    bool valid = (s < 28) && (v >= -1.0f) && (v <= (float)L);
    v = fmaxf(v, 0.0f);
    int lo = (int)v;                              // floor, v >= 0
    int hi; float fr;
    if (lo >= L - 1) { lo = L - 1; hi = L - 1; fr = 0.0f; }
    else             { hi = lo + 1; fr = v - (float)lo; }
    s_slo[axis][lane] = lo;
    s_shi[axis][lane] = hi;
    s_wlo[axis][lane] = valid ? (1.0f - fr) : 0.0f;
    s_whi[axis][lane] = valid ? fr : 0.0f;

    int mnv = valid ? lo : 0x7fffffff;
    int mxv = valid ? hi : -1;
#pragma unroll
    for (int o = 16; o; o >>= 1) {
        mnv = min(mnv, __shfl_xor_sync(0xffffffffu, mnv, o));
        mxv = max(mxv, __shfl_xor_sync(0xffffffffu, mxv, o));
    }
    int n = (mxv < 0) ? 0 : (mxv - mnv + 1);
    if (n > MAXSPAN) n = MAXSPAN;
    if (mxv < 0) mnv = 0;
    __syncwarp();

    if (axis == 0) {
        float* wy = &g_wy[rl * WSTRIDE];
        for (int j = lane; j < n; j += 32) {
            int idx = mnv + j;
            float w = 0.0f;
            for (int t = 0; t < 28; t++) {        // matches reference sum order
                if (s_slo[0][t] == idx) w += s_wlo[0][t];
                if (s_shi[0][t] == idx) w += s_whi[0][t];
            }
            wy[j] = w * (1.0f / 28.0f);
        }
        if (lane == 0) { sh_y0 = mnv; sh_ny = n; }
    } else {
        int x0al  = mnv & ~3;
        int shift = mnv - x0al;
        int nxp   = (n > 0) ? ((shift + n + 3) & ~3) : 0;
        float* wx = &g_wx[rl * WSTRIDE];
        for (int j = lane; j < nxp; j += 32) {
            int k = j - shift;
            float w = 0.0f;
            if (k >= 0 && k < n) {
                int idx = mnv + k;
                for (int t = 0; t < 28; t++) {
                    if (s_slo[1][t] == idx) w += s_wlo[1][t];
                    if (s_shi[1][t] == idx) w += s_whi[1][t];
                }
            }
            wx[j] = w * (1.0f / 28.0f);
        }
        if (lane == 0) { sh_x0al = x0al; sh_nx4 = nxp >> 2; }
    }
    __syncthreads();
    if (threadIdx.x == 0) {
        int ny  = sh_ny;
        int nx4 = sh_nx4;
        g_meta[rl] = make_int4(ny, nx4, sh_y0 * p.W[lvl] + sh_x0al, 0);
        int d = nx4 > 0 ? nx4 : 1;
        g_magic[rl] = (0x100000000ULL + (unsigned long long)d - 1) /
                      (unsigned long long)d;
    }
}

// 1D grid of R*4*8 blocks, LEVEL-MAJOR (all lvl0 blocks first, then lvl1, ...)
// so the fattest blocks launch first and the tail backfills with tiny ones.
// 128 threads = 4 warps; channel group = 32 channels; warp: 8 ch in 2 passes.
__global__ __launch_bounds__(128, 8)
void roi_main_kernel(Params p, const int* __restrict__ bids,
                     float* __restrict__ out, int R) {
    // bid -> (lvl, r, group): per-level block count = R*8
    const int bid    = blockIdx.x;
    const int perlvl = R * 8;
    const int lvl    = bid / perlvl;
    const int within = bid - lvl * perlvl;
    const int r      = within >> 3;
    const int group  = within & 7;
    const int rl     = r * 4 + lvl;

    const int W   = p.W[lvl];
    const int HW  = p.H[lvl] * W;
    const int C   = p.C;

    __shared__ float  s_wy[MAXSPAN];
    __shared__ float4 s_wx4[WSTRIDE / 4];

    const int4 m = g_meta[rl];
    const int ny = m.x, nx4 = m.y;
    const unsigned long long magic = g_magic[rl];

    const int tid = threadIdx.x;
    for (int i = tid; i < ny; i += 128) s_wy[i] = g_wy[rl * WSTRIDE + i];
    for (int i = tid; i < nx4; i += 128)
        s_wx4[i] = ((const float4*)&g_wx[rl * WSTRIDE])[i];
    __syncthreads();

    const int total = ny * nx4;
    const int b = __ldg(&bids[r]);
    const float* __restrict__ fb = p.feat[lvl] + (size_t)b * C * HW + m.z;

    const int warp = tid >> 5, lane = tid & 31;
    const int cbase = group * 32 + warp * 8;
    const int outbase = r * 4 * C + lvl * C;
    const unsigned W4 = (unsigned)(W >> 2);

#pragma unroll
    for (int k = 0; k < 2; k++) {
        const int c = cbase + k * 4;
        const float4* __restrict__ f0 = (const float4*)(fb + (size_t)c * HW);
        const float4* __restrict__ f1 = (const float4*)(fb + (size_t)(c + 1) * HW);
        const float4* __restrict__ f2 = (const float4*)(fb + (size_t)(c + 2) * HW);
        const float4* __restrict__ f3 = (const float4*)(fb + (size_t)(c + 3) * HW);
        float a0 = 0.f, a1 = 0.f, a2 = 0.f, a3 = 0.f;
        for (int i = lane; i < total; i += 32) {
            unsigned yy  = (unsigned)(((unsigned long long)(unsigned)i * magic) >> 32);
            unsigned xx4 = (unsigned)i - yy * (unsigned)nx4;
            int off = (int)(yy * W4 + xx4);
            float  wy = s_wy[yy];
            float4 wx = s_wx4[xx4];
            float4 w4 = make_float4(wy * wx.x, wy * wx.y, wy * wx.z, wy * wx.w);
            float4 v0 = __ldg(f0 + off);
            float4 v1 = __ldg(f1 + off);
            float4 v2 = __ldg(f2 + off);
            float4 v3 = __ldg(f3 + off);
            a0 = fmaf(w4.x, v0.x, fmaf(w4.y, v0.y, fmaf(w4.z, v0.z, fmaf(w4.w, v0.w, a0))));
            a1 = fmaf(w4.x, v1.x, fmaf(w4.y, v1.y, fmaf(w4.z, v1.z, fmaf(w4.w, v1.w, a1))));
            a2 = fmaf(w4.x, v2.x, fmaf(w4.y, v2.y, fmaf(w4.z, v2.z, fmaf(w4.w, v2.w, a2))));
            a3 = fmaf(w4.x, v3.x, fmaf(w4.y, v3.y, fmaf(w4.z, v3.z, fmaf(w4.w, v3.w, a3))));
        }
#pragma unroll
        for (int o = 16; o; o >>= 1) {
            a0 += __shfl_xor_sync(0xffffffffu, a0, o);
            a1 += __shfl_xor_sync(0xffffffffu, a1, o);
            a2 += __shfl_xor_sync(0xffffffffu, a2, o);
            a3 += __shfl_xor_sync(0xffffffffu, a3, o);
        }
        if (lane == 0) {
            out[outbase + c + 0] = a0;
            out[outbase + c + 1] = a1;
            out[outbase + c + 2] = a2;
            out[outbase + c + 3] = a3;
        }
    }
}

extern "C" void kernel_launch(void* const* d_in, const int* in_sizes, int n_in,
                              void* d_out, int out_size) {
    const int B = 2, C = 256;
    Params p;
    for (int i = 0; i < 4; i++) {
        p.feat[i] = (const float*)d_in[i];
        long npix = (long)in_sizes[i] / ((long)B * C);
        int Hh = (int)(sqrt((double)npix * 5.0 / 8.0) + 0.5);  // 800:1280 aspect
        int Ww = (int)(npix / Hh);
        p.H[i] = Hh;
        p.W[i] = Ww;
        p.scale[i] = 0.25f / (float)(1 << i);
    }
    p.C = C;
    const int R = in_sizes[4] / 4;
    const float* boxes = (const float*)d_in[4];
    const int*   bids  = (const int*)d_in[5];

    prep_kernel<<<R * 4, 64>>>(p, boxes);
    roi_main_kernel<<<R * 4 * 8, 128>>>(p, bids, (float*)d_out, R);
}